// round 3
// baseline (speedup 1.0000x reference)
#include <cuda_runtime.h>

namespace {
constexpr int THREADS = 256;
constexpr int CH_STRIDE = 64 * 4 * 16 * 2 * 8;     // 65536 floats / batch
constexpr int NU = 2 * 4 * 2 * 8 * 16;             // 2048
constexpr int PRED_STRIDE = NU + 2 * 2 * 8 * 16;   // 2560
constexpr int A_LD = 65;
constexpr int NRHS = 16;
constexpr int CH_J = 64;       // j per chunk
constexpr int NCHUNK = 2;
constexpr int XOFF = 64 * 64;  // d=1 plane offset (floats) inside sxre/sxim

// dynamic smem (floats)
constexpr int OFF_A   = 0;                       // 64*65 float2  = 8320 f
constexpr int OFF_RHS = OFF_A + 64 * A_LD * 2;   // 64*16 float2  = 2048 f
constexpr int OFF_XRE = OFF_RHS + 64 * NRHS * 2; // [2][64][64]   = 8192 f
constexpr int OFF_XIM = OFF_XRE + 8192;          // 8192 f
constexpr int OFF_U   = OFF_XIM + 8192;          // [8][64] float2 = 1024 f
constexpr int OFF_W   = OFF_U + 1024;            // [64][4]        = 256 f
constexpr int SMEM_FLOATS = OFF_W + 256;
constexpr size_t SMEM_BYTES = (size_t)SMEM_FLOATS * 4;   // 112,128 B

typedef unsigned long long u64t;
}

__device__ __forceinline__ u64t pk2(float x, float y) {
    u64t r; asm("mov.b64 %0,{%1,%2};" : "=l"(r) : "f"(x), "f"(y)); return r;
}
__device__ __forceinline__ void f2fma(u64t& d, u64t a, u64t b) {
    asm("fma.rn.f32x2 %0,%1,%2,%0;" : "+l"(d) : "l"(a), "l"(b));
}
__device__ __forceinline__ float2 up2(u64t v) {
    float2 f; asm("mov.b64 {%0,%1},%2;" : "=f"(f.x), "=f"(f.y) : "l"(v)); return f;
}

__global__ void __launch_bounds__(THREADS, 2)
uw2v_kernel(const float* __restrict__ channel,
            const float* __restrict__ pred,
            float2* __restrict__ out)
{
    extern __shared__ float smf[];
    float2* sA   = (float2*)(smf + OFF_A);
    float2* srhs = (float2*)(smf + OFF_RHS);
    float*  sxre = smf + OFF_XRE;
    float*  sxim = smf + OFF_XIM;
    float2* su   = (float2*)(smf + OFF_U);
    float*  sw   = smf + OFF_W;

    __shared__ u64t   s_keys[2];
    __shared__ float2 wpart[8];
    __shared__ float2 s_trU;
    __shared__ float  s_scale;

    const int b   = blockIdx.x;
    const int tid = threadIdx.x;
    const float* ch = channel + (size_t)b * CH_STRIDE;
    const float* pr = pred    + (size_t)b * PRED_STRIDE;

    // warp tile: 4 t-groups x 8 s-groups per warp -> 1 wavefront per LDS each side
    const int warp = tid >> 5, lane = tid & 31;
    const int ty = ((warp & 3) << 2) | (lane >> 3);   // 0..15
    const int tx = ((warp >> 2) << 3) | (lane & 7);   // 0..15
    const int t0 = ty * 4, s0 = tx * 4;

    u64t accre[2][4], accim[2][4];
    #pragma unroll
    for (int p = 0; p < 2; p++)
        #pragma unroll
        for (int s = 0; s < 4; s++) { accre[p][s] = 0ull; accim[p][s] = 0ull; }

    float2 rhsacc[4] = {{0,0},{0,0},{0,0},{0,0}};
    float trre = 0.f, trim = 0.f;

    for (int c = 0; c < NCHUNK; c++) {
        // ---- load U chunk (512 float2) and W chunk (256 f) ----
        #pragma unroll
        for (int h = 0; h < 2; h++) {
            int idx = tid + 256 * h;
            int rd = idx >> 6, jj = idx & 63;
            int f = c * 8 + (jj >> 3), k = jj & 7;
            int base = (rd * 16 + f) * 16 + k;
            su[idx] = make_float2(pr[base], pr[base + 8]);
        }
        {
            int jw = tid >> 2, de = tid & 3;
            int f = c * 8 + (jw >> 3), k = jw & 7;
            sw[tid] = pr[NU + (de * 16 + f) * 8 + k];
        }
        __syncthreads();

        // ---- phase 1: X[t,d,jj] = sum_r conj(H) * U ----
        {
            int t = tid & 63;
            int fb = tid >> 6;
            #pragma unroll
            for (int h = 0; h < 2; h++) {
                int fl = fb + h * 4;
                const float* chp = ch + t * 1024 + (c * 8 + fl) * 16;
                float xr[2][8], xi[2][8];
                #pragma unroll
                for (int d = 0; d < 2; d++)
                    #pragma unroll
                    for (int k = 0; k < 8; k++) { xr[d][k] = 0.f; xi[d][k] = 0.f; }
                #pragma unroll
                for (int r = 0; r < 4; r++) {
                    float4 h0 = *(const float4*)(chp + r * 256);
                    float4 h1 = *(const float4*)(chp + r * 256 + 4);
                    float4 g0 = *(const float4*)(chp + r * 256 + 8);
                    float4 g1 = *(const float4*)(chp + r * 256 + 12);
                    float hre[8] = {h0.x,h0.y,h0.z,h0.w,h1.x,h1.y,h1.z,h1.w};
                    float him[8] = {g0.x,g0.y,g0.z,g0.w,g1.x,g1.y,g1.z,g1.w};
                    #pragma unroll
                    for (int d = 0; d < 2; d++) {
                        const float2* uptr = su + (r * 2 + d) * 64 + fl * 8;
                        #pragma unroll
                        for (int k = 0; k < 8; k++) {
                            float2 u = uptr[k];
                            xr[d][k] += hre[k] * u.x + him[k] * u.y;
                            xi[d][k] += hre[k] * u.y - him[k] * u.x;
                        }
                    }
                }
                #pragma unroll
                for (int d = 0; d < 2; d++)
                    #pragma unroll
                    for (int k = 0; k < 8; k++) {
                        int jj = fl * 8 + k;
                        sxre[d * XOFF + jj * 64 + t] = xr[d][k];
                        sxim[d * XOFF + jj * 64 + t] = xi[d][k];
                    }
            }
        }
        // ---- trU accumulate (one (r,jj) per thread) ----
        {
            int r = tid >> 6, jj = tid & 63;
            float2 u0 = su[(r * 2) * 64 + jj];
            float2 u1 = su[(r * 2 + 1) * 64 + jj];
            const float* wj = sw + jj * 4;
            float cr = u0.x * u1.x + u0.y * u1.y;
            float ci = u0.y * u1.x - u0.x * u1.y;
            trre += wj[0] * (u0.x*u0.x + u0.y*u0.y) + wj[3] * (u1.x*u1.x + u1.y*u1.y)
                  + (wj[1] + wj[2]) * cr;
            trim += (wj[1] - wj[2]) * ci;
        }
        __syncthreads();

        // ---- rhs accumulate: rhs[t,e,k] += sum_f X[t,d,f,k] W[d,e,f,k] ----
        #pragma unroll
        for (int q = 0; q < 4; q++) {
            int item = tid + 256 * q;
            int t = item >> 4, cc = item & 15, e = cc >> 3, k = cc & 7;
            float sxr = 0.f, sxi = 0.f;
            #pragma unroll
            for (int fl = 0; fl < 8; fl++) {
                int jj = fl * 8 + k;
                float w0 = sw[jj * 4 + e];
                float w1 = sw[jj * 4 + 2 + e];
                sxr += sxre[jj * 64 + t] * w0 + sxre[XOFF + jj * 64 + t] * w1;
                sxi += sxim[jj * 64 + t] * w0 + sxim[XOFF + jj * 64 + t] * w1;
            }
            rhsacc[q].x += sxr; rhsacc[q].y += sxi;
        }

        // ---- quad GEMM: acc[t,s] += sum_{d,jj} X[t,d,jj] * (W conj(X))[d,jj,s] ----
        #pragma unroll 2
        for (int jj = 0; jj < CH_J; jj++) {
            float4 wv = *(const float4*)(sw + jj * 4);   // w00,w01,w10,w11
            ulonglong2 ar0 = *(const ulonglong2*)(sxre + jj * 64 + t0);
            ulonglong2 ai0 = *(const ulonglong2*)(sxim + jj * 64 + t0);
            ulonglong2 ar1 = *(const ulonglong2*)(sxre + XOFF + jj * 64 + t0);
            ulonglong2 ai1 = *(const ulonglong2*)(sxim + XOFF + jj * 64 + t0);
            float4 br0 = *(const float4*)(sxre + jj * 64 + s0);
            float4 bi0 = *(const float4*)(sxim + jj * 64 + s0);
            float4 br1 = *(const float4*)(sxre + XOFF + jj * 64 + s0);
            float4 bi1 = *(const float4*)(sxim + XOFF + jj * 64 + s0);
            float br0a[4] = {br0.x,br0.y,br0.z,br0.w};
            float bi0a[4] = {bi0.x,bi0.y,bi0.z,bi0.w};
            float br1a[4] = {br1.x,br1.y,br1.z,br1.w};
            float bi1a[4] = {bi1.x,bi1.y,bi1.z,bi1.w};
            #pragma unroll
            for (int s = 0; s < 4; s++) {
                float e0r = wv.x * br0a[s] + wv.y * br1a[s];
                float e0i = wv.x * bi0a[s] + wv.y * bi1a[s];
                float e1r = wv.z * br0a[s] + wv.w * br1a[s];
                float e1i = wv.z * bi0a[s] + wv.w * bi1a[s];
                u64t E0r = pk2(e0r, e0r), E0i = pk2(e0i, e0i), N0i = pk2(-e0i, -e0i);
                u64t E1r = pk2(e1r, e1r), E1i = pk2(e1i, e1i), N1i = pk2(-e1i, -e1i);
                // d=0: acc.re += ar*e_r + ai*e_i ; acc.im += ai*e_r - ar*e_i
                f2fma(accre[0][s], ar0.x, E0r); f2fma(accre[0][s], ai0.x, E0i);
                f2fma(accim[0][s], ai0.x, E0r); f2fma(accim[0][s], ar0.x, N0i);
                f2fma(accre[1][s], ar0.y, E0r); f2fma(accre[1][s], ai0.y, E0i);
                f2fma(accim[1][s], ai0.y, E0r); f2fma(accim[1][s], ar0.y, N0i);
                // d=1
                f2fma(accre[0][s], ar1.x, E1r); f2fma(accre[0][s], ai1.x, E1i);
                f2fma(accim[0][s], ai1.x, E1r); f2fma(accim[0][s], ar1.x, N1i);
                f2fma(accre[1][s], ar1.y, E1r); f2fma(accre[1][s], ai1.y, E1i);
                f2fma(accim[1][s], ai1.y, E1r); f2fma(accim[1][s], ar1.y, N1i);
            }
        }
        __syncthreads();   // X/su/sw reused next chunk
    }

    // ---- trU reduction ----
    #pragma unroll
    for (int o = 16; o; o >>= 1) {
        trre += __shfl_down_sync(0xffffffffu, trre, o);
        trim += __shfl_down_sync(0xffffffffu, trim, o);
    }
    if (lane == 0) wpart[warp] = make_float2(trre, trim);
    __syncthreads();
    if (tid == 0) {
        float sx = 0.f, sy = 0.f;
        #pragma unroll
        for (int i = 0; i < 8; i++) { sx += wpart[i].x; sy += wpart[i].y; }
        s_trU = make_float2(0.1f * sx, 0.1f * sy);
        s_keys[0] = 0ull;
    }
    __syncthreads();

    // ---- write A (acc + trU*I) and rhs ----
    {
        float2 trU = s_trU;
        #pragma unroll
        for (int p = 0; p < 2; p++)
            #pragma unroll
            for (int s = 0; s < 4; s++) {
                float2 re2 = up2(accre[p][s]);
                float2 im2 = up2(accim[p][s]);
                int t = t0 + p * 2;
                int col = s0 + s;
                float2 v0 = make_float2(re2.x, im2.x);
                float2 v1 = make_float2(re2.y, im2.y);
                if (t == col)     { v0.x += trU.x; v0.y += trU.y; }
                if (t + 1 == col) { v1.x += trU.x; v1.y += trU.y; }
                sA[t * A_LD + col]       = v0;
                sA[(t + 1) * A_LD + col] = v1;
            }
        #pragma unroll
        for (int q = 0; q < 4; q++) srhs[tid + 256 * q] = rhsacc[q];
    }
    __syncthreads();

    // ---- initial pivot for column 0 ----
    if (tid < 64) {
        float2 a = sA[tid * A_LD];
        float m = fabsf(a.x) + fabsf(a.y);
        atomicMax(&s_keys[0], ((u64t)__float_as_uint(m) << 32) | (unsigned)tid);
    }
    __syncthreads();

    // ---- Gauss-Jordan, pipelined pivot, 2 syncs/iter ----
    for (int i = 0; i < 64; i++) {
        const int piv = (int)(s_keys[i & 1] & 63ull);
        float2 dpv = sA[piv * A_LD + i];
        float inv = 1.f / (dpv.x * dpv.x + dpv.y * dpv.y);
        const float2 pinv = make_float2(dpv.x * inv, -dpv.y * inv);

        // swap + normalize (<= 80 items, one per thread)
        {
            int tot = (64 - i) + NRHS;
            if (tid < tot) {
                if (tid < 64 - i) {
                    int col = i + tid;
                    float2 old_i = sA[i * A_LD + col];
                    float2 pv    = sA[piv * A_LD + col];
                    sA[i * A_LD + col] = make_float2(pv.x * pinv.x - pv.y * pinv.y,
                                                     pv.x * pinv.y + pv.y * pinv.x);
                    if (piv != i) sA[piv * A_LD + col] = old_i;
                } else {
                    int cc = tid - (64 - i);
                    float2 old_i = srhs[i * NRHS + cc];
                    float2 pv    = srhs[piv * NRHS + cc];
                    srhs[i * NRHS + cc] = make_float2(pv.x * pinv.x - pv.y * pinv.y,
                                                      pv.x * pinv.y + pv.y * pinv.x);
                    if (piv != i) srhs[piv * NRHS + cc] = old_i;
                }
            }
            if (tid == 0) s_keys[(i + 1) & 1] = 0ull;
        }
        __syncthreads();

        // eliminate + fold next-column pivot search
        {
            int r = tid >> 2, cg = tid & 3;
            if (r != i) {
                float2 f = sA[r * A_LD + i];
                for (int col = i + 1 + cg; col < 64; col += 4) {
                    float2 p = sA[i * A_LD + col];
                    float2 a = sA[r * A_LD + col];
                    a.x -= f.x * p.x - f.y * p.y;
                    a.y -= f.x * p.y + f.y * p.x;
                    sA[r * A_LD + col] = a;
                    if (col == i + 1 && r > i) {
                        float m = fabsf(a.x) + fabsf(a.y);
                        atomicMax(&s_keys[(i + 1) & 1],
                                  ((u64t)__float_as_uint(m) << 32) | (unsigned)r);
                    }
                }
                #pragma unroll
                for (int cc = cg; cc < NRHS; cc += 4) {
                    float2 p = srhs[i * NRHS + cc];
                    float2 a = srhs[r * NRHS + cc];
                    a.x -= f.x * p.x - f.y * p.y;
                    a.y -= f.x * p.y + f.y * p.x;
                    srhs[r * NRHS + cc] = a;
                }
            }
        }
        __syncthreads();
    }

    // ---- normalize + write out ----
    float ss = 0.f;
    #pragma unroll
    for (int q = 0; q < 4; q++) {
        float2 v = srhs[tid + 256 * q];
        ss += v.x * v.x + v.y * v.y;
    }
    #pragma unroll
    for (int o = 16; o; o >>= 1) ss += __shfl_down_sync(0xffffffffu, ss, o);
    if (lane == 0) wpart[warp].x = ss;
    __syncthreads();
    if (tid == 0) {
        float tot = 0.f;
        #pragma unroll
        for (int i = 0; i < 8; i++) tot += wpart[i].x;
        s_scale = rsqrtf(tot);   // P=1: combined factor = 1/||V0||
    }
    __syncthreads();
    const float sc = s_scale;
    float2* op = out + (size_t)b * (64 * NRHS);
    #pragma unroll
    for (int q = 0; q < 4; q++) {
        float2 v = srhs[tid + 256 * q];
        op[tid + 256 * q] = make_float2(v.x * sc, v.y * sc);
    }
}

extern "C" void kernel_launch(void* const* d_in, const int* in_sizes, int n_in,
                              void* d_out, int out_size)
{
    const float* channel = (const float*)d_in[0];
    const float* pred    = (const float*)d_in[1];
    cudaFuncSetAttribute(uw2v_kernel, cudaFuncAttributeMaxDynamicSharedMemorySize,
                         (int)SMEM_BYTES);
    uw2v_kernel<<<256, THREADS, SMEM_BYTES, 0>>>(channel, pred, (float2*)d_out);
}

// round 4
// speedup vs baseline: 1.0073x; 1.0073x over previous
#include <cuda_runtime.h>

namespace {
constexpr int THREADS = 512;
constexpr int CH_STRIDE = 64 * 4 * 16 * 2 * 8;     // 65536 floats / batch
constexpr int NU = 2 * 4 * 2 * 8 * 16;             // 2048
constexpr int PRED_STRIDE = NU + 2 * 2 * 8 * 16;   // 2560
constexpr int A_LD = 65;
constexpr int NRHS = 16;
constexpr int CH_J = 64;       // j per chunk
constexpr int NCHUNK = 2;
constexpr int XOFF = 64 * 64;  // d=1 plane offset (floats)

// dynamic smem (floats)
constexpr int OFF_A   = 0;                       // 64*65 float2  = 8320 f
constexpr int OFF_RHS = OFF_A + 64 * A_LD * 2;   // 64*16 float2  = 2048 f
constexpr int OFF_XRE = OFF_RHS + 64 * NRHS * 2; // [2][64][64]   = 8192 f
constexpr int OFF_XIM = OFF_XRE + 8192;          // 8192 f
constexpr int OFF_U   = OFF_XIM + 8192;          // [8][64] float2 = 1024 f
constexpr int OFF_W   = OFF_U + 1024;            // [64][4]        = 256 f
constexpr int SMEM_FLOATS = OFF_W + 256;
constexpr size_t SMEM_BYTES = (size_t)SMEM_FLOATS * 4;   // 112,128 B

typedef unsigned long long u64t;
}

__device__ __forceinline__ u64t pk2(float x, float y) {
    u64t r; asm("mov.b64 %0,{%1,%2};" : "=l"(r) : "f"(x), "f"(y)); return r;
}
__device__ __forceinline__ void f2fma(u64t& d, u64t a, u64t b) {
    asm("fma.rn.f32x2 %0,%1,%2,%0;" : "+l"(d) : "l"(a), "l"(b));
}
__device__ __forceinline__ float2 up2(u64t v) {
    float2 f; asm("mov.b64 {%0,%1},%2;" : "=f"(f.x), "=f"(f.y) : "l"(v)); return f;
}

__global__ void __launch_bounds__(THREADS, 2)
uw2v_kernel(const float* __restrict__ channel,
            const float* __restrict__ pred,
            float2* __restrict__ out)
{
    extern __shared__ float smf[];
    float2* sA   = (float2*)(smf + OFF_A);
    float2* srhs = (float2*)(smf + OFF_RHS);
    float*  sxre = smf + OFF_XRE;
    float*  sxim = smf + OFF_XIM;
    float2* su   = (float2*)(smf + OFF_U);
    float*  sw   = smf + OFF_W;

    __shared__ u64t   s_keys[2];
    __shared__ float2 wpart[16];
    __shared__ float2 s_trU;
    __shared__ float  s_scale;

    const int b   = blockIdx.x;
    const int tid = threadIdx.x;
    const float* ch = channel + (size_t)b * CH_STRIDE;
    const float* pr = pred    + (size_t)b * PRED_STRIDE;

    const int warp = tid >> 5, lane = tid & 31;
    // 16 t-groups x 32 s-groups
    const int ty = ((warp & 3) << 2) | (lane >> 3);   // 0..15
    const int tx = ((warp >> 2) << 3) | (lane & 7);   // 0..31
    const int t0 = ty * 4, s0 = tx * 2;

    u64t accre[2][2], accim[2][2];
    #pragma unroll
    for (int p = 0; p < 2; p++)
        #pragma unroll
        for (int s = 0; s < 2; s++) { accre[p][s] = 0ull; accim[p][s] = 0ull; }

    float2 rhsacc[2] = {{0,0},{0,0}};
    float trre = 0.f, trim = 0.f;

    for (int c = 0; c < NCHUNK; c++) {
        // ---- load U chunk (512 float2) and W chunk (256 f) ----
        {
            int rd = tid >> 6, jj = tid & 63;
            int f = c * 8 + (jj >> 3), k = jj & 7;
            int base = (rd * 16 + f) * 16 + k;
            su[tid] = make_float2(pr[base], pr[base + 8]);
            if (tid < 256) {
                int jw = tid >> 2, de = tid & 3;
                int fw = c * 8 + (jw >> 3), kw = jw & 7;
                sw[tid] = pr[NU + (de * 16 + fw) * 8 + kw];
            }
        }
        __syncthreads();

        // ---- phase 1: X[t,d,jj] = sum_r conj(H) * U  (one (t,fl) per thread) ----
        {
            int t = tid & 63;
            int fl = tid >> 6;                         // 0..7
            const float* chp = ch + t * 1024 + (c * 8 + fl) * 16;
            #pragma unroll
            for (int d = 0; d < 2; d++) {
                float xr[8], xi[8];
                #pragma unroll
                for (int k = 0; k < 8; k++) { xr[k] = 0.f; xi[k] = 0.f; }
                #pragma unroll
                for (int r = 0; r < 4; r++) {
                    float4 h0 = *(const float4*)(chp + r * 256);
                    float4 h1 = *(const float4*)(chp + r * 256 + 4);
                    float4 g0 = *(const float4*)(chp + r * 256 + 8);
                    float4 g1 = *(const float4*)(chp + r * 256 + 12);
                    float hre[8] = {h0.x,h0.y,h0.z,h0.w,h1.x,h1.y,h1.z,h1.w};
                    float him[8] = {g0.x,g0.y,g0.z,g0.w,g1.x,g1.y,g1.z,g1.w};
                    const float2* uptr = su + (r * 2 + d) * 64 + fl * 8;
                    #pragma unroll
                    for (int k = 0; k < 8; k++) {
                        float2 u = uptr[k];
                        xr[k] += hre[k] * u.x + him[k] * u.y;
                        xi[k] += hre[k] * u.y - him[k] * u.x;
                    }
                }
                #pragma unroll
                for (int k = 0; k < 8; k++) {
                    int jj = fl * 8 + k;
                    sxre[d * XOFF + jj * 64 + t] = xr[k];
                    sxim[d * XOFF + jj * 64 + t] = xi[k];
                }
            }
        }
        // ---- trU accumulate (256 threads: one (r,jj) each) ----
        if (tid < 256) {
            int r = tid >> 6, jj = tid & 63;
            float2 u0 = su[(r * 2) * 64 + jj];
            float2 u1 = su[(r * 2 + 1) * 64 + jj];
            const float* wj = sw + jj * 4;
            float cr = u0.x * u1.x + u0.y * u1.y;
            float ci = u0.y * u1.x - u0.x * u1.y;
            trre += wj[0] * (u0.x*u0.x + u0.y*u0.y) + wj[3] * (u1.x*u1.x + u1.y*u1.y)
                  + (wj[1] + wj[2]) * cr;
            trim += (wj[1] - wj[2]) * ci;
        }
        __syncthreads();

        // ---- rhs accumulate ----
        #pragma unroll
        for (int q = 0; q < 2; q++) {
            int item = tid + 512 * q;
            int t = item >> 4, cc = item & 15, e = cc >> 3, k = cc & 7;
            float sxr = 0.f, sxi = 0.f;
            #pragma unroll
            for (int fl = 0; fl < 8; fl++) {
                int jj = fl * 8 + k;
                float w0 = sw[jj * 4 + e];
                float w1 = sw[jj * 4 + 2 + e];
                sxr += sxre[jj * 64 + t] * w0 + sxre[XOFF + jj * 64 + t] * w1;
                sxi += sxim[jj * 64 + t] * w0 + sxim[XOFF + jj * 64 + t] * w1;
            }
            rhsacc[q].x += sxr; rhsacc[q].y += sxi;
        }

        // ---- quad GEMM ----
        const float* pre = sxre + t0;
        const float* pim = sxim + t0;
        const float* qre = sxre + s0;
        const float* qim = sxim + s0;
        #pragma unroll 2
        for (int jj = 0; jj < CH_J; jj++) {
            float4 wv = *(const float4*)(sw + jj * 4);
            ulonglong2 ar0 = *(const ulonglong2*)(pre + jj * 64);
            ulonglong2 ai0 = *(const ulonglong2*)(pim + jj * 64);
            ulonglong2 ar1 = *(const ulonglong2*)(pre + XOFF + jj * 64);
            ulonglong2 ai1 = *(const ulonglong2*)(pim + XOFF + jj * 64);
            float2 br0 = *(const float2*)(qre + jj * 64);
            float2 bi0 = *(const float2*)(qim + jj * 64);
            float2 br1 = *(const float2*)(qre + XOFF + jj * 64);
            float2 bi1 = *(const float2*)(qim + XOFF + jj * 64);
            float br0a[2] = {br0.x, br0.y};
            float bi0a[2] = {bi0.x, bi0.y};
            float br1a[2] = {br1.x, br1.y};
            float bi1a[2] = {bi1.x, bi1.y};
            #pragma unroll
            for (int s = 0; s < 2; s++) {
                float e0r = wv.x * br0a[s] + wv.y * br1a[s];
                float e0i = wv.x * bi0a[s] + wv.y * bi1a[s];
                float e1r = wv.z * br0a[s] + wv.w * br1a[s];
                float e1i = wv.z * bi0a[s] + wv.w * bi1a[s];
                u64t E0r = pk2(e0r, e0r), E0i = pk2(e0i, e0i), N0i = pk2(-e0i, -e0i);
                u64t E1r = pk2(e1r, e1r), E1i = pk2(e1i, e1i), N1i = pk2(-e1i, -e1i);
                f2fma(accre[0][s], ar0.x, E0r); f2fma(accre[0][s], ai0.x, E0i);
                f2fma(accim[0][s], ai0.x, E0r); f2fma(accim[0][s], ar0.x, N0i);
                f2fma(accre[1][s], ar0.y, E0r); f2fma(accre[1][s], ai0.y, E0i);
                f2fma(accim[1][s], ai0.y, E0r); f2fma(accim[1][s], ar0.y, N0i);
                f2fma(accre[0][s], ar1.x, E1r); f2fma(accre[0][s], ai1.x, E1i);
                f2fma(accim[0][s], ai1.x, E1r); f2fma(accim[0][s], ar1.x, N1i);
                f2fma(accre[1][s], ar1.y, E1r); f2fma(accre[1][s], ai1.y, E1i);
                f2fma(accim[1][s], ai1.y, E1r); f2fma(accim[1][s], ar1.y, N1i);
            }
        }
        __syncthreads();
    }

    // ---- trU reduction ----
    #pragma unroll
    for (int o = 16; o; o >>= 1) {
        trre += __shfl_down_sync(0xffffffffu, trre, o);
        trim += __shfl_down_sync(0xffffffffu, trim, o);
    }
    if (lane == 0) wpart[warp] = make_float2(trre, trim);
    __syncthreads();
    if (tid == 0) {
        float sx = 0.f, sy = 0.f;
        #pragma unroll
        for (int i = 0; i < 16; i++) { sx += wpart[i].x; sy += wpart[i].y; }
        s_trU = make_float2(0.1f * sx, 0.1f * sy);
        s_keys[0] = 0ull;
    }
    __syncthreads();

    // ---- write A (acc + trU*I) and rhs ----
    {
        float2 trU = s_trU;
        #pragma unroll
        for (int p = 0; p < 2; p++)
            #pragma unroll
            for (int s = 0; s < 2; s++) {
                float2 re2 = up2(accre[p][s]);
                float2 im2 = up2(accim[p][s]);
                int t = t0 + p * 2;
                int col = s0 + s;
                float2 v0 = make_float2(re2.x, im2.x);
                float2 v1 = make_float2(re2.y, im2.y);
                if (t == col)     { v0.x += trU.x; v0.y += trU.y; }
                if (t + 1 == col) { v1.x += trU.x; v1.y += trU.y; }
                sA[t * A_LD + col]       = v0;
                sA[(t + 1) * A_LD + col] = v1;
            }
        #pragma unroll
        for (int q = 0; q < 2; q++) srhs[tid + 512 * q] = rhsacc[q];
    }
    __syncthreads();

    // ---- initial pivot for column 0 ----
    if (tid < 64) {
        float2 a = sA[tid * A_LD];
        float m = fabsf(a.x) + fabsf(a.y);
        atomicMax(&s_keys[0], ((u64t)__float_as_uint(m) << 32) | (unsigned)tid);
    }
    __syncthreads();

    // ---- Gauss-Jordan, pipelined pivot, 2 syncs/iter ----
    for (int i = 0; i < 64; i++) {
        const int piv = (int)(s_keys[i & 1] & 63ull);
        float2 dpv = sA[piv * A_LD + i];
        float inv = 1.f / (dpv.x * dpv.x + dpv.y * dpv.y);
        const float2 pinv = make_float2(dpv.x * inv, -dpv.y * inv);

        // swap + normalize
        {
            int tot = (64 - i) + NRHS;
            if (tid < tot) {
                if (tid < 64 - i) {
                    int col = i + tid;
                    float2 old_i = sA[i * A_LD + col];
                    float2 pv    = sA[piv * A_LD + col];
                    sA[i * A_LD + col] = make_float2(pv.x * pinv.x - pv.y * pinv.y,
                                                     pv.x * pinv.y + pv.y * pinv.x);
                    if (piv != i) sA[piv * A_LD + col] = old_i;
                } else {
                    int cc = tid - (64 - i);
                    float2 old_i = srhs[i * NRHS + cc];
                    float2 pv    = srhs[piv * NRHS + cc];
                    srhs[i * NRHS + cc] = make_float2(pv.x * pinv.x - pv.y * pinv.y,
                                                      pv.x * pinv.y + pv.y * pinv.x);
                    if (piv != i) srhs[piv * NRHS + cc] = old_i;
                }
            }
            if (tid == 0) s_keys[(i + 1) & 1] = 0ull;
        }
        __syncthreads();

        // eliminate + fold next-column pivot search (8 threads per row)
        {
            int r = tid >> 3, cg = tid & 7;
            if (r != i) {
                float2 f = sA[r * A_LD + i];
                for (int col = i + 1 + cg; col < 64; col += 8) {
                    float2 p = sA[i * A_LD + col];
                    float2 a = sA[r * A_LD + col];
                    a.x -= f.x * p.x - f.y * p.y;
                    a.y -= f.x * p.y + f.y * p.x;
                    sA[r * A_LD + col] = a;
                    if (col == i + 1 && r > i) {
                        float m = fabsf(a.x) + fabsf(a.y);
                        atomicMax(&s_keys[(i + 1) & 1],
                                  ((u64t)__float_as_uint(m) << 32) | (unsigned)r);
                    }
                }
                #pragma unroll
                for (int cc = cg; cc < NRHS; cc += 8) {
                    float2 p = srhs[i * NRHS + cc];
                    float2 a = srhs[r * NRHS + cc];
                    a.x -= f.x * p.x - f.y * p.y;
                    a.y -= f.x * p.y + f.y * p.x;
                    srhs[r * NRHS + cc] = a;
                }
            }
        }
        __syncthreads();
    }

    // ---- normalize + write out ----
    float ss = 0.f;
    #pragma unroll
    for (int q = 0; q < 2; q++) {
        float2 v = srhs[tid + 512 * q];
        ss += v.x * v.x + v.y * v.y;
    }
    #pragma unroll
    for (int o = 16; o; o >>= 1) ss += __shfl_down_sync(0xffffffffu, ss, o);
    if (lane == 0) wpart[warp].x = ss;
    __syncthreads();
    if (tid == 0) {
        float tot = 0.f;
        #pragma unroll
        for (int i = 0; i < 16; i++) tot += wpart[i].x;
        s_scale = rsqrtf(tot);   // P=1: combined factor = 1/||V0||
    }
    __syncthreads();
    const float sc = s_scale;
    float2* op = out + (size_t)b * (64 * NRHS);
    #pragma unroll
    for (int q = 0; q < 2; q++) {
        float2 v = srhs[tid + 512 * q];
        op[tid + 512 * q] = make_float2(v.x * sc, v.y * sc);
    }
}

extern "C" void kernel_launch(void* const* d_in, const int* in_sizes, int n_in,
                              void* d_out, int out_size)
{
    const float* channel = (const float*)d_in[0];
    const float* pred    = (const float*)d_in[1];
    cudaFuncSetAttribute(uw2v_kernel, cudaFuncAttributeMaxDynamicSharedMemorySize,
                         (int)SMEM_BYTES);
    uw2v_kernel<<<256, THREADS, SMEM_BYTES, 0>>>(channel, pred, (float2*)d_out);
}

// round 5
// speedup vs baseline: 1.2265x; 1.2175x over previous
#include <cuda_runtime.h>

namespace {
constexpr int THREADS = 512;
constexpr int CH_STRIDE = 64 * 4 * 16 * 2 * 8;     // 65536 floats / batch
constexpr int NU = 2 * 4 * 2 * 8 * 16;             // 2048
constexpr int PRED_STRIDE = NU + 2 * 2 * 8 * 16;   // 2560
constexpr int A_LD = 66;       // even -> 16B-aligned rows
constexpr int NRHS = 16;
constexpr int CH_J = 32;       // j per chunk
constexpr int NCHUNK = 4;
constexpr int XOFF = CH_J * 64;  // 2048: d=1 plane offset (floats)

// dynamic smem (floats)
constexpr int OFF_A   = 0;                        // 64*66 f2 = 8448 f
constexpr int OFF_RHS = OFF_A + 64 * A_LD * 2;    // 2048 f
constexpr int OFF_XRE = OFF_RHS + 64 * NRHS * 2;  // 4096 f
constexpr int OFF_XIM = OFF_XRE + 4096;
constexpr int OFF_ZRE = OFF_XIM + 4096;
constexpr int OFF_ZIM = OFF_ZRE + 4096;
constexpr int OFF_U   = OFF_ZIM + 4096;           // [8][32] f2 = 512 f
constexpr int OFF_W   = OFF_U + 512;              // [32][4]   = 128 f
constexpr int SMEM_FLOATS = OFF_W + 128;
constexpr size_t SMEM_BYTES = (size_t)SMEM_FLOATS * 4;   // 110,080 B

typedef unsigned long long u64t;
}

__device__ __forceinline__ u64t pk2(float x, float y) {
    u64t r; asm("mov.b64 %0,{%1,%2};" : "=l"(r) : "f"(x), "f"(y)); return r;
}
__device__ __forceinline__ void f2fma(u64t& d, u64t a, u64t b) {
    asm("fma.rn.f32x2 %0,%1,%2,%0;" : "+l"(d) : "l"(a), "l"(b));
}
__device__ __forceinline__ float2 up2(u64t v) {
    float2 f; asm("mov.b64 {%0,%1},%2;" : "=f"(f.x), "=f"(f.y) : "l"(v)); return f;
}

__global__ void __launch_bounds__(THREADS, 2)
uw2v_kernel(const float* __restrict__ channel,
            const float* __restrict__ pred,
            float2* __restrict__ out)
{
    extern __shared__ float smf[];
    float2* sA   = (float2*)(smf + OFF_A);
    float2* srhs = (float2*)(smf + OFF_RHS);
    float*  sxre = smf + OFF_XRE;
    float*  sxim = smf + OFF_XIM;
    float*  szre = smf + OFF_ZRE;
    float*  szim = smf + OFF_ZIM;
    float2* su   = (float2*)(smf + OFF_U);
    float*  sw   = smf + OFF_W;

    __shared__ float2 prow[72];    // skewed pivot row: idx = col + (col>>3)
    __shared__ float2 prhs[16];
    __shared__ float2 fcol[64];
    __shared__ float2 wpart[16];
    __shared__ u64t   s_keys[2];
    __shared__ float  s_scale;

    const int b   = blockIdx.x;
    const int tid = threadIdx.x;
    const float* ch = channel + (size_t)b * CH_STRIDE;
    const float* pr = pred    + (size_t)b * PRED_STRIDE;

    const int warp = tid >> 5, lane = tid & 31;
    const int group = tid >> 8;          // 0/1: jj-split halves
    const int gtid  = tid & 255;
    const int ty = gtid >> 4, tx = gtid & 15;
    const int t0 = ty * 4, s0 = tx * 4;

    u64t accre[2][4], accim[2][4];
    #pragma unroll
    for (int p = 0; p < 2; p++)
        #pragma unroll
        for (int s = 0; s < 4; s++) { accre[p][s] = 0ull; accim[p][s] = 0ull; }

    float2 rhsacc[2] = {{0,0},{0,0}};
    float trre = 0.f, trim = 0.f;

    for (int c = 0; c < NCHUNK; c++) {
        // ---- (A) load U chunk (256 f2) and W chunk (128 f) ----
        if (tid < 256) {
            int rd = tid >> 5, jj = tid & 31;
            int f = c * 4 + (jj >> 3), k = jj & 7;
            int base = (rd * 16 + f) * 16 + k;
            su[tid] = make_float2(pr[base], pr[base + 8]);
            if (tid < 128) {
                int jw = tid >> 2, de = tid & 3;
                int fw = c * 4 + (jw >> 3), kw = jw & 7;
                sw[tid] = pr[NU + (de * 16 + fw) * 8 + kw];
            }
        }
        __syncthreads();

        // ---- (B) phase 1: X[d][jj][t] = sum_r conj(H)*U ; one (t,fl,d)/thread ----
        {
            int t  = tid & 63;
            int fl = (tid >> 6) & 3;
            int d  = tid >> 8;
            const float* chp = ch + t * 1024 + (c * 4 + fl) * 16;
            float xr[8], xi[8];
            #pragma unroll
            for (int k = 0; k < 8; k++) { xr[k] = 0.f; xi[k] = 0.f; }
            #pragma unroll
            for (int r = 0; r < 4; r++) {
                float4 h0 = *(const float4*)(chp + r * 256);
                float4 h1 = *(const float4*)(chp + r * 256 + 4);
                float4 g0 = *(const float4*)(chp + r * 256 + 8);
                float4 g1 = *(const float4*)(chp + r * 256 + 12);
                float hre[8] = {h0.x,h0.y,h0.z,h0.w,h1.x,h1.y,h1.z,h1.w};
                float him[8] = {g0.x,g0.y,g0.z,g0.w,g1.x,g1.y,g1.z,g1.w};
                const float2* uptr = su + (r * 2 + d) * 32 + fl * 8;
                #pragma unroll
                for (int k = 0; k < 8; k++) {
                    float2 u = uptr[k];
                    xr[k] += hre[k] * u.x + him[k] * u.y;
                    xi[k] += hre[k] * u.y - him[k] * u.x;
                }
            }
            #pragma unroll
            for (int k = 0; k < 8; k++) {
                int jj = fl * 8 + k;
                sxre[d * XOFF + jj * 64 + t] = xr[k];
                sxim[d * XOFF + jj * 64 + t] = xi[k];
            }
        }
        __syncthreads();

        // ---- (C) Z = W*conj(X), rhs accumulate, trU accumulate ----
        #pragma unroll
        for (int h = 0; h < 8; h++) {
            int idx = tid + 512 * h;                    // d*2048 + jj*64 + s
            int d = idx >> 11, jj = (idx >> 6) & 31, s = idx & 63;
            float w0 = sw[jj * 4 + d * 2];
            float w1 = sw[jj * 4 + d * 2 + 1];
            szre[idx] =  w0 * sxre[jj * 64 + s] + w1 * sxre[XOFF + jj * 64 + s];
            szim[idx] = -(w0 * sxim[jj * 64 + s] + w1 * sxim[XOFF + jj * 64 + s]);
        }
        #pragma unroll
        for (int q = 0; q < 2; q++) {
            int item = tid + 512 * q;
            int t = item >> 4, cc = item & 15, e = cc >> 3, k = cc & 7;
            float sxr = 0.f, sxi = 0.f;
            #pragma unroll
            for (int fl = 0; fl < 4; fl++) {
                int jj = fl * 8 + k;
                float w0 = sw[jj * 4 + e];
                float w1 = sw[jj * 4 + 2 + e];
                sxr += sxre[jj * 64 + t] * w0 + sxre[XOFF + jj * 64 + t] * w1;
                sxi += sxim[jj * 64 + t] * w0 + sxim[XOFF + jj * 64 + t] * w1;
            }
            rhsacc[q].x += sxr; rhsacc[q].y += sxi;
        }
        if (tid < 128) {
            int r = tid >> 5, jj = tid & 31;
            float2 u0 = su[(r * 2) * 32 + jj];
            float2 u1 = su[(r * 2 + 1) * 32 + jj];
            const float* wj = sw + jj * 4;
            float cr = u0.x * u1.x + u0.y * u1.y;
            float ci = u0.y * u1.x - u0.x * u1.y;
            trre += wj[0] * (u0.x*u0.x + u0.y*u0.y) + wj[3] * (u1.x*u1.x + u1.y*u1.y)
                  + (wj[1] + wj[2]) * cr;
            trim += (wj[1] - wj[2]) * ci;
        }
        __syncthreads();

        // ---- (D) quad GEMM: group handles its 16 jj with 4x4 tile ----
        {
            const int jb = group * 16, je = jb + 16;
            #pragma unroll 1
            for (int jj = jb; jj < je; jj++) {
                #pragma unroll
                for (int d = 0; d < 2; d++) {
                    ulonglong2 ar = *(const ulonglong2*)(sxre + d * XOFF + jj * 64 + t0);
                    ulonglong2 ai = *(const ulonglong2*)(sxim + d * XOFF + jj * 64 + t0);
                    float4 zr = *(const float4*)(szre + d * XOFF + jj * 64 + s0);
                    float4 zi = *(const float4*)(szim + d * XOFF + jj * 64 + s0);
                    float zra[4] = {zr.x, zr.y, zr.z, zr.w};
                    float zia[4] = {zi.x, zi.y, zi.z, zi.w};
                    #pragma unroll
                    for (int s = 0; s < 4; s++) {
                        u64t Zr  = pk2(zra[s], zra[s]);
                        u64t Zi  = pk2(zia[s], zia[s]);
                        u64t Zni = pk2(-zia[s], -zia[s]);
                        f2fma(accre[0][s], ar.x, Zr);  f2fma(accre[0][s], ai.x, Zni);
                        f2fma(accim[0][s], ar.x, Zi);  f2fma(accim[0][s], ai.x, Zr);
                        f2fma(accre[1][s], ar.y, Zr);  f2fma(accre[1][s], ai.y, Zni);
                        f2fma(accim[1][s], ar.y, Zi);  f2fma(accim[1][s], ai.y, Zr);
                    }
                }
            }
        }
        __syncthreads();
    }

    // ---- trU warp reduce + group-1 partial store + rhs store ----
    #pragma unroll
    for (int o = 16; o; o >>= 1) {
        trre += __shfl_down_sync(0xffffffffu, trre, o);
        trim += __shfl_down_sync(0xffffffffu, trim, o);
    }
    if (lane == 0) wpart[warp] = make_float2(trre, trim);

    u64t* scratch = (u64t*)(smf + OFF_XRE);   // 8192 u64 = X/Z region
    if (group == 1) {
        int base = gtid * 32;
        #pragma unroll
        for (int p = 0; p < 2; p++)
            #pragma unroll
            for (int s = 0; s < 4; s++) {
                scratch[base + p * 4 + s]     = accre[p][s];
                scratch[base + 8 + p * 4 + s] = accim[p][s];
            }
    }
    #pragma unroll
    for (int q = 0; q < 2; q++) srhs[tid + 512 * q] = rhsacc[q];
    __syncthreads();

    // ---- group 0 merges partials, writes A (+ trU*I) ----
    if (group == 0) {
        float sx = 0.f, sy = 0.f;
        #pragma unroll
        for (int i = 0; i < 16; i++) { sx += wpart[i].x; sy += wpart[i].y; }
        float2 trU = make_float2(0.1f * sx, 0.1f * sy);
        int base = gtid * 32;
        #pragma unroll
        for (int p = 0; p < 2; p++)
            #pragma unroll
            for (int s = 0; s < 4; s++) {
                float2 re2 = up2(accre[p][s]);
                float2 im2 = up2(accim[p][s]);
                float2 ore = up2(scratch[base + p * 4 + s]);
                float2 oim = up2(scratch[base + 8 + p * 4 + s]);
                re2.x += ore.x; re2.y += ore.y;
                im2.x += oim.x; im2.y += oim.y;
                int t = t0 + p * 2, col = s0 + s;
                float2 v0 = make_float2(re2.x, im2.x);
                float2 v1 = make_float2(re2.y, im2.y);
                if (t == col)     { v0.x += trU.x; v0.y += trU.y; }
                if (t + 1 == col) { v1.x += trU.x; v1.y += trU.y; }
                sA[t * A_LD + col]       = v0;
                sA[(t + 1) * A_LD + col] = v1;
            }
    }
    if (tid == 0) s_keys[0] = 0ull;
    __syncthreads();

    // ---- register-resident Gauss-Jordan (virtual pivoting) ----
    const int r = tid >> 3, cg = tid & 7;
    float2 a[8]; float2 rr[2];
    #pragma unroll
    for (int j = 0; j < 8; j++) a[j] = sA[r * A_LD + cg * 8 + j];
    {
        float4 t4 = *(const float4*)(srhs + r * NRHS + cg * 2);
        rr[0] = make_float2(t4.x, t4.y);
        rr[1] = make_float2(t4.z, t4.w);
    }
    bool used = false; int mycol = 0;
    if (cg == 0) {
        float m = fabsf(a[0].x) + fabsf(a[0].y);
        atomicMax(&s_keys[0], ((u64t)__float_as_uint(m) << 32) | (unsigned)r);
    }
    __syncthreads();

    for (int oct = 0; oct < 8; oct++) {
        #pragma unroll
        for (int jl = 0; jl < 8; jl++) {
            const int i = oct * 8 + jl;
            // step 1: broadcast multiplier column + raw pivot row
            const int piv = (int)(s_keys[i & 1] & 63ull);
            if (tid == 0) s_keys[(i + 1) & 1] = 0ull;
            if (cg == oct) fcol[r] = a[jl];
            if (r == piv) {
                #pragma unroll
                for (int j = 0; j < 8; j++) prow[cg * 9 + j] = a[j];
                prhs[cg * 2]     = rr[0];
                prhs[cg * 2 + 1] = rr[1];
            }
            __syncthreads();
            // step 2: normalize pivot row / eliminate everyone else (in regs)
            float2 dv = prow[oct * 9 + jl];
            float inv = 1.f / (dv.x * dv.x + dv.y * dv.y);
            float2 pinv = make_float2(dv.x * inv, -dv.y * inv);
            if (r == piv) {
                #pragma unroll
                for (int j = 0; j < 8; j++) {
                    float2 v = a[j];
                    a[j] = make_float2(v.x * pinv.x - v.y * pinv.y,
                                       v.x * pinv.y + v.y * pinv.x);
                }
                float2 v0 = rr[0], v1 = rr[1];
                rr[0] = make_float2(v0.x * pinv.x - v0.y * pinv.y,
                                    v0.x * pinv.y + v0.y * pinv.x);
                rr[1] = make_float2(v1.x * pinv.x - v1.y * pinv.y,
                                    v1.x * pinv.y + v1.y * pinv.x);
                used = true; mycol = i;
            } else {
                float2 fc = fcol[r];
                float2 f = make_float2(fc.x * pinv.x - fc.y * pinv.y,
                                       fc.x * pinv.y + fc.y * pinv.x);
                #pragma unroll
                for (int j = 0; j < 8; j++) {
                    float2 p = prow[cg * 9 + j];
                    a[j].x -= f.x * p.x - f.y * p.y;
                    a[j].y -= f.x * p.y + f.y * p.x;
                }
                float2 p0 = prhs[cg * 2], p1 = prhs[cg * 2 + 1];
                rr[0].x -= f.x * p0.x - f.y * p0.y;
                rr[0].y -= f.x * p0.y + f.y * p0.x;
                rr[1].x -= f.x * p1.x - f.y * p1.y;
                rr[1].y -= f.x * p1.y + f.y * p1.x;
            }
            if (i < 63) {
                const int nc = i + 1;
                if (!used && cg == (nc >> 3)) {
                    float2 v = a[nc & 7];
                    float m = fabsf(v.x) + fabsf(v.y);
                    atomicMax(&s_keys[nc & 1],
                              ((u64t)__float_as_uint(m) << 32) | (unsigned)r);
                }
            }
            __syncthreads();
        }
    }

    // ---- scatter solution: X[mycol] = this row's rhs ----
    *(float4*)(srhs + mycol * NRHS + cg * 2) =
        make_float4(rr[0].x, rr[0].y, rr[1].x, rr[1].y);
    __syncthreads();

    // ---- normalize + write out ----
    float ss = 0.f;
    #pragma unroll
    for (int q = 0; q < 2; q++) {
        float2 v = srhs[tid + 512 * q];
        ss += v.x * v.x + v.y * v.y;
    }
    #pragma unroll
    for (int o = 16; o; o >>= 1) ss += __shfl_down_sync(0xffffffffu, ss, o);
    if (lane == 0) wpart[warp].x = ss;
    __syncthreads();
    if (tid == 0) {
        float tot = 0.f;
        #pragma unroll
        for (int i = 0; i < 16; i++) tot += wpart[i].x;
        s_scale = rsqrtf(tot);   // P=1: total factor = 1/||V0||
    }
    __syncthreads();
    const float sc = s_scale;
    float2* op = out + (size_t)b * (64 * NRHS);
    #pragma unroll
    for (int q = 0; q < 2; q++) {
        float2 v = srhs[tid + 512 * q];
        op[tid + 512 * q] = make_float2(v.x * sc, v.y * sc);
    }
}

extern "C" void kernel_launch(void* const* d_in, const int* in_sizes, int n_in,
                              void* d_out, int out_size)
{
    const float* channel = (const float*)d_in[0];
    const float* pred    = (const float*)d_in[1];
    cudaFuncSetAttribute(uw2v_kernel, cudaFuncAttributeMaxDynamicSharedMemorySize,
                         (int)SMEM_BYTES);
    uw2v_kernel<<<256, THREADS, SMEM_BYTES, 0>>>(channel, pred, (float2*)d_out);
}

// round 6
// speedup vs baseline: 1.4936x; 1.2178x over previous
#include <cuda_runtime.h>

namespace {
constexpr int THREADS = 512;
constexpr int CH_STRIDE = 64 * 4 * 16 * 2 * 8;     // 65536 floats / batch
constexpr int NU = 2 * 4 * 2 * 8 * 16;             // 2048
constexpr int PRED_STRIDE = NU + 2 * 2 * 8 * 16;   // 2560
constexpr int A_LD = 66;
constexpr int NRHS = 16;
constexpr int CH_J = 32;       // j per chunk
constexpr int NCHUNK = 4;
constexpr int X_LD  = 68;      // padded jj-stride for X (floats)
constexpr int XOFF2 = 2180;    // padded d-plane stride for X (floats)
constexpr int ZOFF  = 2048;    // d-plane stride for Z (floats), jj stride 64

// dynamic smem (floats)
constexpr int OFF_A   = 0;                        // 64*66 f2 = 8448 f
constexpr int OFF_RHS = OFF_A + 64 * A_LD * 2;    // 2048 f
constexpr int OFF_XRE = OFF_RHS + 64 * NRHS * 2;  // 2*2180 = 4360 f
constexpr int OFF_XIM = OFF_XRE + 2 * XOFF2;      // 4360 f
constexpr int OFF_ZRE = OFF_XIM + 2 * XOFF2;      // 4096 f
constexpr int OFF_ZIM = OFF_ZRE + 4096;           // 4096 f
constexpr int OFF_U   = OFF_ZIM + 4096;           // [8][32] f2 = 512 f
constexpr int OFF_W   = OFF_U + 512;              // [32][4]   = 128 f
constexpr int SMEM_FLOATS = OFF_W + 128;
constexpr size_t SMEM_BYTES = (size_t)SMEM_FLOATS * 4;   // 112,192 B

typedef unsigned long long u64t;
}

__device__ __forceinline__ u64t pk2(float x, float y) {
    u64t r; asm("mov.b64 %0,{%1,%2};" : "=l"(r) : "f"(x), "f"(y)); return r;
}
__device__ __forceinline__ void f2fma(u64t& d, u64t a, u64t b) {
    asm("fma.rn.f32x2 %0,%1,%2,%0;" : "+l"(d) : "l"(a), "l"(b));
}
__device__ __forceinline__ float2 up2(u64t v) {
    float2 f; asm("mov.b64 {%0,%1},%2;" : "=f"(f.x), "=f"(f.y) : "l"(v)); return f;
}

__global__ void __launch_bounds__(THREADS, 2)
uw2v_kernel(const float* __restrict__ channel,
            const float* __restrict__ pred,
            float2* __restrict__ out)
{
    extern __shared__ float smf[];
    float2* sA   = (float2*)(smf + OFF_A);
    float2* srhs = (float2*)(smf + OFF_RHS);
    float*  sxre = smf + OFF_XRE;
    float*  sxim = smf + OFF_XIM;
    float*  szre = smf + OFF_ZRE;
    float*  szim = smf + OFF_ZIM;
    float2* su   = (float2*)(smf + OFF_U);
    float*  sw   = smf + OFF_W;

    __shared__ float2 prow[72];    // skewed pivot row: idx = col + (col>>3)
    __shared__ float2 prhs[16];
    __shared__ float2 fcol[64];
    __shared__ float2 wpart[16];
    __shared__ u64t   s_keys[2];
    __shared__ float  s_scale;

    const int b   = blockIdx.x;
    const int tid = threadIdx.x;
    const float* ch = channel + (size_t)b * CH_STRIDE;
    const float* pr = pred    + (size_t)b * PRED_STRIDE;

    const int warp = tid >> 5, lane = tid & 31;
    const int group = tid >> 8;          // 0/1: jj-split halves
    const int gtid  = tid & 255;
    const int ty = gtid >> 4, tx = gtid & 15;
    const int t0 = ty * 4, s0 = tx * 4;

    // phase-B mapping: warp spans only 4 t values -> 4-line LDG.128
    const int pb_t  = tid >> 3;
    const int pb_fl = (tid >> 2) & 1;
    const int pb_kh = (tid >> 1) & 1;
    const int pb_d  = tid & 1;

    u64t accre[2][4], accim[2][4];
    #pragma unroll
    for (int p = 0; p < 2; p++)
        #pragma unroll
        for (int s = 0; s < 4; s++) { accre[p][s] = 0ull; accim[p][s] = 0ull; }

    float2 rhsacc[2] = {{0,0},{0,0}};
    float trre = 0.f, trim = 0.f;

    for (int c = 0; c < NCHUNK; c++) {
        // ---- (A) load U chunk (256 f2) and W chunk (128 f) ----
        if (tid < 256) {
            int rd = tid >> 5, jj = tid & 31;
            int f = c * 4 + (jj >> 3), k = jj & 7;
            int base = (rd * 16 + f) * 16 + k;
            su[tid] = make_float2(pr[base], pr[base + 8]);
            if (tid < 128) {
                int jw = tid >> 2, de = tid & 3;
                int fw = c * 4 + (jw >> 3), kw = jw & 7;
                sw[tid] = pr[NU + (de * 16 + fw) * 8 + kw];
            }
        }
        __syncthreads();

        // ---- (B) X[d][jj][t] = sum_r conj(H)*U  (coalesced 4-line loads) ----
        #pragma unroll
        for (int fh = 0; fh < 2; fh++) {
            const int flg = fh * 2 + pb_fl;   // 0..3
            const float* chp = ch + pb_t * 1024 + (c * 4 + flg) * 16 + pb_kh * 4;
            float xr[4] = {0.f,0.f,0.f,0.f}, xi[4] = {0.f,0.f,0.f,0.f};
            #pragma unroll
            for (int r = 0; r < 4; r++) {
                float4 hre = *(const float4*)(chp + r * 256);
                float4 him = *(const float4*)(chp + r * 256 + 8);
                const float2* uptr = su + (r * 2 + pb_d) * 32 + flg * 8 + pb_kh * 4;
                float hr[4] = {hre.x, hre.y, hre.z, hre.w};
                float hi[4] = {him.x, him.y, him.z, him.w};
                #pragma unroll
                for (int kk = 0; kk < 4; kk++) {
                    float2 u = uptr[kk];
                    xr[kk] += hr[kk] * u.x + hi[kk] * u.y;
                    xi[kk] += hr[kk] * u.y - hi[kk] * u.x;
                }
            }
            #pragma unroll
            for (int kk = 0; kk < 4; kk++) {
                int jj = flg * 8 + pb_kh * 4 + kk;
                sxre[pb_d * XOFF2 + jj * X_LD + pb_t] = xr[kk];
                sxim[pb_d * XOFF2 + jj * X_LD + pb_t] = xi[kk];
            }
        }
        __syncthreads();

        // ---- (C) Z = W*conj(X), rhs accumulate, trU accumulate ----
        #pragma unroll
        for (int h = 0; h < 8; h++) {
            int idx = tid + 512 * h;                    // d*2048 + jj*64 + s
            int d = idx >> 11, jj = (idx >> 6) & 31, s = idx & 63;
            float w0 = sw[jj * 4 + d * 2];
            float w1 = sw[jj * 4 + d * 2 + 1];
            szre[idx] =  w0 * sxre[jj * X_LD + s] + w1 * sxre[XOFF2 + jj * X_LD + s];
            szim[idx] = -(w0 * sxim[jj * X_LD + s] + w1 * sxim[XOFF2 + jj * X_LD + s]);
        }
        #pragma unroll
        for (int q = 0; q < 2; q++) {
            int item = tid + 512 * q;
            int t = item >> 4, cc = item & 15, e = cc >> 3, k = cc & 7;
            float sxr = 0.f, sxi = 0.f;
            #pragma unroll
            for (int fl = 0; fl < 4; fl++) {
                int jj = fl * 8 + k;
                float w0 = sw[jj * 4 + e];
                float w1 = sw[jj * 4 + 2 + e];
                sxr += sxre[jj * X_LD + t] * w0 + sxre[XOFF2 + jj * X_LD + t] * w1;
                sxi += sxim[jj * X_LD + t] * w0 + sxim[XOFF2 + jj * X_LD + t] * w1;
            }
            rhsacc[q].x += sxr; rhsacc[q].y += sxi;
        }
        if (tid < 128) {
            int r = tid >> 5, jj = tid & 31;
            float2 u0 = su[(r * 2) * 32 + jj];
            float2 u1 = su[(r * 2 + 1) * 32 + jj];
            const float* wj = sw + jj * 4;
            float cr = u0.x * u1.x + u0.y * u1.y;
            float ci = u0.y * u1.x - u0.x * u1.y;
            trre += wj[0] * (u0.x*u0.x + u0.y*u0.y) + wj[3] * (u1.x*u1.x + u1.y*u1.y)
                  + (wj[1] + wj[2]) * cr;
            trim += (wj[1] - wj[2]) * ci;
        }
        __syncthreads();

        // ---- (D) quad GEMM: group handles its 16 jj with 4x4 tile ----
        {
            const int jb = group * 16, je = jb + 16;
            #pragma unroll 1
            for (int jj = jb; jj < je; jj++) {
                #pragma unroll
                for (int d = 0; d < 2; d++) {
                    ulonglong2 ar = *(const ulonglong2*)(sxre + d * XOFF2 + jj * X_LD + t0);
                    ulonglong2 ai = *(const ulonglong2*)(sxim + d * XOFF2 + jj * X_LD + t0);
                    float4 zr = *(const float4*)(szre + d * ZOFF + jj * 64 + s0);
                    float4 zi = *(const float4*)(szim + d * ZOFF + jj * 64 + s0);
                    float zra[4] = {zr.x, zr.y, zr.z, zr.w};
                    float zia[4] = {zi.x, zi.y, zi.z, zi.w};
                    #pragma unroll
                    for (int s = 0; s < 4; s++) {
                        u64t Zr  = pk2(zra[s], zra[s]);
                        u64t Zi  = pk2(zia[s], zia[s]);
                        u64t Zni = pk2(-zia[s], -zia[s]);
                        f2fma(accre[0][s], ar.x, Zr);  f2fma(accre[0][s], ai.x, Zni);
                        f2fma(accim[0][s], ar.x, Zi);  f2fma(accim[0][s], ai.x, Zr);
                        f2fma(accre[1][s], ar.y, Zr);  f2fma(accre[1][s], ai.y, Zni);
                        f2fma(accim[1][s], ar.y, Zi);  f2fma(accim[1][s], ai.y, Zr);
                    }
                }
            }
        }
        __syncthreads();
    }

    // ---- trU warp reduce + group-1 partial store + rhs store ----
    #pragma unroll
    for (int o = 16; o; o >>= 1) {
        trre += __shfl_down_sync(0xffffffffu, trre, o);
        trim += __shfl_down_sync(0xffffffffu, trim, o);
    }
    if (lane == 0) wpart[warp] = make_float2(trre, trim);

    u64t* scratch = (u64t*)(smf + OFF_XRE);   // X/Z region reuse
    if (group == 1) {
        int base = gtid * 32;
        #pragma unroll
        for (int p = 0; p < 2; p++)
            #pragma unroll
            for (int s = 0; s < 4; s++) {
                scratch[base + p * 4 + s]     = accre[p][s];
                scratch[base + 8 + p * 4 + s] = accim[p][s];
            }
    }
    #pragma unroll
    for (int q = 0; q < 2; q++) srhs[tid + 512 * q] = rhsacc[q];
    __syncthreads();

    // ---- group 0 merges partials, writes A (+ trU*I) ----
    if (group == 0) {
        float sx = 0.f, sy = 0.f;
        #pragma unroll
        for (int i = 0; i < 16; i++) { sx += wpart[i].x; sy += wpart[i].y; }
        float2 trU = make_float2(0.1f * sx, 0.1f * sy);
        int base = gtid * 32;
        #pragma unroll
        for (int p = 0; p < 2; p++)
            #pragma unroll
            for (int s = 0; s < 4; s++) {
                float2 re2 = up2(accre[p][s]);
                float2 im2 = up2(accim[p][s]);
                float2 ore = up2(scratch[base + p * 4 + s]);
                float2 oim = up2(scratch[base + 8 + p * 4 + s]);
                re2.x += ore.x; re2.y += ore.y;
                im2.x += oim.x; im2.y += oim.y;
                int t = t0 + p * 2, col = s0 + s;
                float2 v0 = make_float2(re2.x, im2.x);
                float2 v1 = make_float2(re2.y, im2.y);
                if (t == col)     { v0.x += trU.x; v0.y += trU.y; }
                if (t + 1 == col) { v1.x += trU.x; v1.y += trU.y; }
                sA[t * A_LD + col]       = v0;
                sA[(t + 1) * A_LD + col] = v1;
            }
    }
    if (tid == 0) s_keys[0] = 0ull;
    __syncthreads();

    // ---- register-resident Gauss-Jordan (virtual pivoting) ----
    const int r = tid >> 3, cg = tid & 7;
    float2 a[8]; float2 rr[2];
    #pragma unroll
    for (int j = 0; j < 8; j++) a[j] = sA[r * A_LD + cg * 8 + j];
    {
        float4 t4 = *(const float4*)(srhs + r * NRHS + cg * 2);
        rr[0] = make_float2(t4.x, t4.y);
        rr[1] = make_float2(t4.z, t4.w);
    }
    bool used = false; int mycol = 0;
    if (cg == 0) {
        float m = fabsf(a[0].x) + fabsf(a[0].y);
        atomicMax(&s_keys[0], ((u64t)__float_as_uint(m) << 32) | (unsigned)r);
    }
    __syncthreads();

    for (int oct = 0; oct < 8; oct++) {
        #pragma unroll
        for (int jl = 0; jl < 8; jl++) {
            const int i = oct * 8 + jl;
            const int piv = (int)(s_keys[i & 1] & 63ull);
            if (tid == 0) s_keys[(i + 1) & 1] = 0ull;
            if (cg == oct) fcol[r] = a[jl];
            if (r == piv) {
                #pragma unroll
                for (int j = 0; j < 8; j++) prow[cg * 9 + j] = a[j];
                prhs[cg * 2]     = rr[0];
                prhs[cg * 2 + 1] = rr[1];
            }
            __syncthreads();
            float2 dv = prow[oct * 9 + jl];
            float inv = 1.f / (dv.x * dv.x + dv.y * dv.y);
            float2 pinv = make_float2(dv.x * inv, -dv.y * inv);
            if (r == piv) {
                #pragma unroll
                for (int j = 0; j < 8; j++) {
                    float2 v = a[j];
                    a[j] = make_float2(v.x * pinv.x - v.y * pinv.y,
                                       v.x * pinv.y + v.y * pinv.x);
                }
                float2 v0 = rr[0], v1 = rr[1];
                rr[0] = make_float2(v0.x * pinv.x - v0.y * pinv.y,
                                    v0.x * pinv.y + v0.y * pinv.x);
                rr[1] = make_float2(v1.x * pinv.x - v1.y * pinv.y,
                                    v1.x * pinv.y + v1.y * pinv.x);
                used = true; mycol = i;
            } else {
                float2 fc = fcol[r];
                float2 f = make_float2(fc.x * pinv.x - fc.y * pinv.y,
                                       fc.x * pinv.y + fc.y * pinv.x);
                #pragma unroll
                for (int j = 0; j < 8; j++) {
                    float2 p = prow[cg * 9 + j];
                    a[j].x -= f.x * p.x - f.y * p.y;
                    a[j].y -= f.x * p.y + f.y * p.x;
                }
                float2 p0 = prhs[cg * 2], p1 = prhs[cg * 2 + 1];
                rr[0].x -= f.x * p0.x - f.y * p0.y;
                rr[0].y -= f.x * p0.y + f.y * p0.x;
                rr[1].x -= f.x * p1.x - f.y * p1.y;
                rr[1].y -= f.x * p1.y + f.y * p1.x;
            }
            if (i < 63) {
                const int nc = i + 1;
                if (!used && cg == (nc >> 3)) {
                    float2 v = a[nc & 7];
                    float m = fabsf(v.x) + fabsf(v.y);
                    atomicMax(&s_keys[nc & 1],
                              ((u64t)__float_as_uint(m) << 32) | (unsigned)r);
                }
            }
            __syncthreads();
        }
    }

    // ---- scatter solution: X[mycol] = this row's rhs ----
    *(float4*)(srhs + mycol * NRHS + cg * 2) =
        make_float4(rr[0].x, rr[0].y, rr[1].x, rr[1].y);
    __syncthreads();

    // ---- normalize + write out ----
    float ss = 0.f;
    #pragma unroll
    for (int q = 0; q < 2; q++) {
        float2 v = srhs[tid + 512 * q];
        ss += v.x * v.x + v.y * v.y;
    }
    #pragma unroll
    for (int o = 16; o; o >>= 1) ss += __shfl_down_sync(0xffffffffu, ss, o);
    if (lane == 0) wpart[warp].x = ss;
    __syncthreads();
    if (tid == 0) {
        float tot = 0.f;
        #pragma unroll
        for (int i = 0; i < 16; i++) tot += wpart[i].x;
        s_scale = rsqrtf(tot);   // P=1: total factor = 1/||V0||
    }
    __syncthreads();
    const float sc = s_scale;
    float2* op = out + (size_t)b * (64 * NRHS);
    #pragma unroll
    for (int q = 0; q < 2; q++) {
        float2 v = srhs[tid + 512 * q];
        op[tid + 512 * q] = make_float2(v.x * sc, v.y * sc);
    }
}

extern "C" void kernel_launch(void* const* d_in, const int* in_sizes, int n_in,
                              void* d_out, int out_size)
{
    const float* channel = (const float*)d_in[0];
    const float* pred    = (const float*)d_in[1];
    cudaFuncSetAttribute(uw2v_kernel, cudaFuncAttributeMaxDynamicSharedMemorySize,
                         (int)SMEM_BYTES);
    uw2v_kernel<<<256, THREADS, SMEM_BYTES, 0>>>(channel, pred, (float2*)d_out);
}